// round 12
// baseline (speedup 1.0000x reference)
#include <cuda_runtime.h>
#include <cuda_bf16.h>
#include <math.h>
#include <stdint.h>

#define BB 4
#define TT 2048
#define DD 2048
#define HH 16
#define GG 4
#define KKD 128
#define NTOK (BB*TT)          /* 8192 */
#define QW (HH*KKD)           /* 2048 */
#define KVW (GG*KKD)          /* 512  */

// ---------------- scratch (static device globals; no allocation) ----------------
__device__ float g_q[(size_t)NTOK*QW];
__device__ float g_k[(size_t)NTOK*KVW];
__device__ int   g_pos[NTOK];

__device__ __nv_bfloat16 g_qhi[(size_t)NTOK*QW];
__device__ __nv_bfloat16 g_qlo[(size_t)NTOK*QW];
__device__ __nv_bfloat16 g_khi[(size_t)NTOK*KVW];
__device__ __nv_bfloat16 g_klo[(size_t)NTOK*KVW];
__device__ __nv_bfloat16 g_vhi[(size_t)NTOK*KVW];
__device__ __nv_bfloat16 g_vlo[(size_t)NTOK*KVW];

__device__ __nv_bfloat16 g_hid_hi[(size_t)NTOK*DD];
__device__ __nv_bfloat16 g_hid_lo[(size_t)NTOK*DD];
__device__ __nv_bfloat16 g_att_hi[(size_t)NTOK*QW];
__device__ __nv_bfloat16 g_att_lo[(size_t)NTOK*QW];
__device__ __nv_bfloat16 g_wq_hi[(size_t)QW*DD];
__device__ __nv_bfloat16 g_wq_lo[(size_t)QW*DD];
__device__ __nv_bfloat16 g_wk_hi[(size_t)KVW*DD];
__device__ __nv_bfloat16 g_wk_lo[(size_t)KVW*DD];
__device__ __nv_bfloat16 g_wv_hi[(size_t)KVW*DD];
__device__ __nv_bfloat16 g_wv_lo[(size_t)KVW*DD];
__device__ __nv_bfloat16 g_wo_hi[(size_t)DD*QW];
__device__ __nv_bfloat16 g_wo_lo[(size_t)DD*QW];

// ---------------- base-ISA PTX helpers ----------------
__device__ __forceinline__ uint32_t smem_u32(const void* p) {
    uint32_t a;
    asm("{ .reg .u64 t; cvta.to.shared.u64 t, %1; cvt.u32.u64 %0, t; }" : "=r"(a) : "l"(p));
    return a;
}
__device__ __forceinline__ void cp16(uint32_t saddr, const void* g) {
    asm volatile("cp.async.cg.shared.global [%0], [%1], 16;" :: "r"(saddr), "l"(g) : "memory");
}
__device__ __forceinline__ void ldm_x4(uint32_t& r0, uint32_t& r1, uint32_t& r2, uint32_t& r3, uint32_t a) {
    asm volatile("ldmatrix.sync.aligned.m8n8.x4.shared.b16 {%0,%1,%2,%3}, [%4];"
                 : "=r"(r0), "=r"(r1), "=r"(r2), "=r"(r3) : "r"(a));
}
__device__ __forceinline__ void ldm_x4t(uint32_t& r0, uint32_t& r1, uint32_t& r2, uint32_t& r3, uint32_t a) {
    asm volatile("ldmatrix.sync.aligned.m8n8.x4.trans.shared.b16 {%0,%1,%2,%3}, [%4];"
                 : "=r"(r0), "=r"(r1), "=r"(r2), "=r"(r3) : "r"(a));
}
__device__ __forceinline__ void mma16816(float* d, const uint32_t* a, const uint32_t* b) {
    asm volatile(
        "mma.sync.aligned.m16n8k16.row.col.f32.bf16.bf16.f32 "
        "{%0,%1,%2,%3}, {%4,%5,%6,%7}, {%8,%9}, {%0,%1,%2,%3};"
        : "+f"(d[0]), "+f"(d[1]), "+f"(d[2]), "+f"(d[3])
        : "r"(a[0]), "r"(a[1]), "r"(a[2]), "r"(a[3]), "r"(b[0]), "r"(b[1]));
}
__device__ __forceinline__ uint32_t pkhl(float x, float y) {
    __nv_bfloat162 t = __floats2bfloat162_rn(x, y);
    return *reinterpret_cast<uint32_t*>(&t);
}
__device__ __forceinline__ float bfres(float x) {
    return x - __bfloat162float(__float2bfloat16(x));
}

// ---------------- positions from sorted segment ids ----------------
__global__ void pos_kernel(const int* __restrict__ seg) {
    int idx = blockIdx.x * blockDim.x + threadIdx.x;
    if (idx >= NTOK) return;
    int b = idx / TT, t = idx % TT;
    const int* s = seg + b * TT;
    int v = s[t];
    int lo = 0, hi = t;
    while (lo < hi) { int mid = (lo + hi) >> 1; if (s[mid] < v) lo = mid + 1; else hi = mid; }
    g_pos[idx] = t - lo;
}

// ---------------- elementwise fp32 -> (hi, lo) bf16 split ----------------
__global__ void split_kernel(const float* __restrict__ x,
                             __nv_bfloat16* __restrict__ hi,
                             __nv_bfloat16* __restrict__ lo, int n4) {
    int i = blockIdx.x * blockDim.x + threadIdx.x;
    if (i >= n4) return;
    float4 v = ((const float4*)x)[i];
    __nv_bfloat16 h0 = __float2bfloat16(v.x);
    __nv_bfloat16 h1 = __float2bfloat16(v.y);
    __nv_bfloat16 h2 = __float2bfloat16(v.z);
    __nv_bfloat16 h3 = __float2bfloat16(v.w);
    __nv_bfloat162 ha, hb, la, lb;
    ha.x = h0; ha.y = h1; hb.x = h2; hb.y = h3;
    la.x = __float2bfloat16(v.x - __bfloat162float(h0));
    la.y = __float2bfloat16(v.y - __bfloat162float(h1));
    lb.x = __float2bfloat16(v.z - __bfloat162float(h2));
    lb.y = __float2bfloat16(v.w - __bfloat162float(h3));
    ((__nv_bfloat162*)hi)[2*i] = ha; ((__nv_bfloat162*)hi)[2*i+1] = hb;
    ((__nv_bfloat162*)lo)[2*i] = la; ((__nv_bfloat162*)lo)[2*i+1] = lb;
}

// ---------------- weight transpose + split: W[Rk,N] -> T[N,Rk] hi/lo bf16 -----
__global__ void tsplit_kernel(const float* __restrict__ W,
                              __nv_bfloat16* __restrict__ hi,
                              __nv_bfloat16* __restrict__ lo, int Rk, int N) {
    __shared__ float tile[32][33];
    int tx = threadIdx.x;
    int x = blockIdx.x * 32 + tx;
    int y0 = blockIdx.y * 32;
    for (int i = threadIdx.y; i < 32; i += 8)
        tile[i][tx] = W[(size_t)(y0 + i) * N + x];
    __syncthreads();
    int k = y0 + tx;
    for (int i = threadIdx.y; i < 32; i += 8) {
        int n = blockIdx.x * 32 + i;
        float val = tile[tx][i];
        __nv_bfloat16 h = __float2bfloat16(val);
        hi[(size_t)n * Rk + k] = h;
        lo[(size_t)n * Rk + k] = __float2bfloat16(val - __bfloat162float(h));
    }
}

// ------- 3xBF16 GEMM core: 128(M) x 256(N) tile, BK=64, 2-stage pipeline ------
// 8 warps, 2(M) x 4(N); warp tile 64x64.
#define ROWB 144                        /* 64 bf16 = 128B data + 16B pad */
#define A_ROWS 128
#define B_ROWS 256
#define OFF_AHI 0
#define OFF_ALO (A_ROWS*ROWB)           /* 18432 */
#define OFF_BHI (2*A_ROWS*ROWB)         /* 36864 */
#define OFF_BLO (OFF_BHI + B_ROWS*ROWB) /* 73728 */
#define GSTAGE (OFF_BLO + B_ROWS*ROWB)  /* 110592 */
#define GSM (2*GSTAGE)                  /* 221184 */
#define NCHUNK 24                       /* 6144 16B-chunks / 256 threads */

__device__ __forceinline__ void gemm_core(
    const __nv_bfloat16* __restrict__ Ahi, const __nv_bfloat16* __restrict__ Alo,
    const __nv_bfloat16* __restrict__ Bhi, const __nv_bfloat16* __restrict__ Blo,
    float* __restrict__ C, __nv_bfloat16* __restrict__ Chi, __nv_bfloat16* __restrict__ Clo,
    int mode, int Ntot, int Kd, int row0, int col0, char* smbuf)
{
    const int tid = threadIdx.x;
    const int wid = tid >> 5, lane = tid & 31;
    const int warp_m = wid >> 2, warp_n = wid & 3;
    const uint32_t smb = smem_u32(smbuf);

    const __nv_bfloat16* gb[4] = {
        Ahi + (size_t)row0 * Kd, Alo + (size_t)row0 * Kd,
        Bhi + (size_t)col0 * Kd, Blo + (size_t)col0 * Kd };

    float acc[4][8][4];
#pragma unroll
    for (int i = 0; i < 4; i++)
#pragma unroll
        for (int j = 0; j < 8; j++)
#pragma unroll
            for (int c = 0; c < 4; c++) acc[i][j][c] = 0.f;

    const int T = Kd >> 6;

    // per-thread cp.async chunk table
    int ld_buf[NCHUNK]; uint32_t ld_soff[NCHUNK]; int ld_row[NCHUNK], ld_c[NCHUNK];
#pragma unroll
    for (int i = 0; i < NCHUNK; i++) {
        int id = tid + (i << 8);            // 0..6143
        int buf, sub;
        uint32_t sbase;
        if (id < 1024)      { buf = 0; sub = id;        sbase = OFF_AHI; }
        else if (id < 2048) { buf = 1; sub = id - 1024; sbase = OFF_ALO; }
        else if (id < 4096) { buf = 2; sub = id - 2048; sbase = OFF_BHI; }
        else                { buf = 3; sub = id - 4096; sbase = OFF_BLO; }
        int row = sub >> 3, c = sub & 7;
        ld_buf[i] = buf; ld_row[i] = row; ld_c[i] = c;
        ld_soff[i] = sbase + (uint32_t)row * ROWB + (uint32_t)c * 16;
    }

#define LOAD_STAGE(t, s) do {                                                   \
    int k0_ = (t) << 6;                                                         \
    _Pragma("unroll")                                                           \
    for (int i_ = 0; i_ < NCHUNK; i_++) {                                       \
        uint32_t sa = smb + (s) * GSTAGE + ld_soff[i_];                         \
        const __nv_bfloat16* g = gb[ld_buf[i_]] +                               \
            (size_t)ld_row[i_] * Kd + k0_ + ld_c[i_] * 8;                       \
        cp16(sa, g);                                                            \
    }                                                                           \
    asm volatile("cp.async.commit_group;" ::: "memory");                        \
} while (0)

    // fragment addressing (bytes)
    const uint32_t aoff = (uint32_t)((warp_m * 64 + (lane & 15)) * ROWB + ((lane >> 4) << 3) * 2);
    // B x4-pair: rows p*16 + (lane&7) + ((lane>>4)<<3), k-half ((lane>>3)&1)*8
    const uint32_t boff = (uint32_t)((warp_n * 64 + (lane & 7) + ((lane >> 4) << 3)) * ROWB
                                     + (((lane >> 3) & 1) << 3) * 2);

    LOAD_STAGE(0, 0);

    for (int t = 0; t < T; t++) {
        int s = t & 1;
        asm volatile("cp.async.wait_group 0;" ::: "memory");
        __syncthreads();
        if (t + 1 < T) LOAD_STAGE(t + 1, s ^ 1);

        uint32_t stg = smb + s * GSTAGE;
#pragma unroll
        for (int k16 = 0; k16 < 4; k16++) {
            uint32_t aA = stg + aoff + k16 * 32;
            uint32_t bA = stg + OFF_BHI + boff + k16 * 32;
            uint32_t ah[4][4], al[4][4], bh[8][2], bl[8][2];
#pragma unroll
            for (int mf = 0; mf < 4; mf++) {
                uint32_t ad = aA + mf * 16 * ROWB;
                ldm_x4(ah[mf][0], ah[mf][1], ah[mf][2], ah[mf][3], ad);
                ldm_x4(al[mf][0], al[mf][1], al[mf][2], al[mf][3], ad + (OFF_ALO - OFF_AHI));
            }
#pragma unroll
            for (int p = 0; p < 4; p++) {
                uint32_t bd = bA + p * 16 * ROWB;
                ldm_x4(bh[2*p][0], bh[2*p][1], bh[2*p+1][0], bh[2*p+1][1], bd);
                ldm_x4(bl[2*p][0], bl[2*p][1], bl[2*p+1][0], bl[2*p+1][1], bd + (OFF_BLO - OFF_BHI));
            }
#pragma unroll
            for (int mf = 0; mf < 4; mf++)
#pragma unroll
                for (int nf = 0; nf < 8; nf++) {
                    mma16816(acc[mf][nf], ah[mf], bh[nf]);
                    mma16816(acc[mf][nf], ah[mf], bl[nf]);
                    mma16816(acc[mf][nf], al[mf], bh[nf]);
                }
        }
    }

    int tr = lane >> 2;
    int tc = (lane & 3) << 1;
    if (mode == 0) {
#pragma unroll
        for (int mf = 0; mf < 4; mf++) {
            int m = row0 + warp_m * 64 + mf * 16 + tr;
#pragma unroll
            for (int nf = 0; nf < 8; nf++) {
                int n = col0 + warp_n * 64 + nf * 8 + tc;
                *(float2*)(C + (size_t)m * Ntot + n) = make_float2(acc[mf][nf][0], acc[mf][nf][1]);
                *(float2*)(C + (size_t)(m + 8) * Ntot + n) = make_float2(acc[mf][nf][2], acc[mf][nf][3]);
            }
        }
    } else {
#pragma unroll
        for (int mf = 0; mf < 4; mf++) {
            int m = row0 + warp_m * 64 + mf * 16 + tr;
#pragma unroll
            for (int nf = 0; nf < 8; nf++) {
                int n = col0 + warp_n * 64 + nf * 8 + tc;
#pragma unroll
                for (int rr = 0; rr < 2; rr++) {
                    float v0 = acc[mf][nf][rr*2], v1 = acc[mf][nf][rr*2+1];
                    __nv_bfloat162 hh, ll;
                    hh.x = __float2bfloat16(v0); hh.y = __float2bfloat16(v1);
                    ll.x = __float2bfloat16(v0 - __bfloat162float(hh.x));
                    ll.y = __float2bfloat16(v1 - __bfloat162float(hh.y));
                    size_t a = (size_t)(m + rr*8) * Ntot + n;
                    *(__nv_bfloat162*)(Chi + a) = hh;
                    *(__nv_bfloat162*)(Clo + a) = ll;
                }
            }
        }
    }
#undef LOAD_STAGE
}

// merged QKV projection: grid.x: 0-7 -> Q, 8-9 -> K, 10-11 -> V (V writes hi/lo)
__global__ __launch_bounds__(256, 1) void qkv_gemm_kernel(
    const __nv_bfloat16* __restrict__ Ahi, const __nv_bfloat16* __restrict__ Alo)
{
    extern __shared__ __align__(128) char smbuf[];
    int cx = blockIdx.x;
    if (cx < 8) {
        gemm_core(Ahi, Alo, g_wq_hi, g_wq_lo, g_q, 0, 0, 0, QW, DD,
                  blockIdx.y * 128, cx * 256, smbuf);
    } else if (cx < 10) {
        gemm_core(Ahi, Alo, g_wk_hi, g_wk_lo, g_k, 0, 0, 0, KVW, DD,
                  blockIdx.y * 128, (cx - 8) * 256, smbuf);
    } else {
        gemm_core(Ahi, Alo, g_wv_hi, g_wv_lo, 0, g_vhi, g_vlo, 1, KVW, DD,
                  blockIdx.y * 128, (cx - 10) * 256, smbuf);
    }
}

__global__ __launch_bounds__(256, 1) void mma_gemm_kernel(
    const __nv_bfloat16* __restrict__ Ahi, const __nv_bfloat16* __restrict__ Alo,
    const __nv_bfloat16* __restrict__ Bhi, const __nv_bfloat16* __restrict__ Blo,
    float* __restrict__ C, int Ntot, int Kd)
{
    extern __shared__ __align__(128) char smbuf[];
    gemm_core(Ahi, Alo, Bhi, Blo, C, 0, 0, 0, Ntot, Kd,
              blockIdx.y * 128, blockIdx.x * 256, smbuf);
}

// ------- fused RMSNorm + RoPE, writes bf16 hi/lo -------
__global__ void normrope_kernel(const float* __restrict__ x, const float* __restrict__ scale,
                                __nv_bfloat16* __restrict__ hi, __nv_bfloat16* __restrict__ lo,
                                int heads) {
    int warp = (blockIdx.x * blockDim.x + threadIdx.x) >> 5;
    int lane = threadIdx.x & 31;
    int token = warp / heads;
    int head = warp % heads;
    const float* p = x + (size_t)token * heads * KKD + head * KKD;

    float4 v = *(const float4*)(p + lane * 4);
    float ss = v.x * v.x + v.y * v.y + v.z * v.z + v.w * v.w;
#pragma unroll
    for (int o = 16; o > 0; o >>= 1) ss += __shfl_xor_sync(0xffffffffu, ss, o);
    float inv = rsqrtf(ss * (1.0f / 128.0f) + 1e-6f);
    float4 sc = *(const float4*)(scale + lane * 4);
    float vv[4];
    vv[0] = v.x * inv * sc.x; vv[1] = v.y * inv * sc.y;
    vv[2] = v.z * inv * sc.z; vv[3] = v.w * inv * sc.w;

    float pf = (float)g_pos[token];
    float out[4];
#pragma unroll
    for (int c = 0; c < 4; c++) {
        int k = lane * 4 + c;
        int j = k & 63;
        float invf = expf(-9.210340371976184f * ((float)j * (1.0f / 64.0f)));
        float sn, cs;
        sincosf(pf * invf, &sn, &cs);
        float partner = __shfl_xor_sync(0xffffffffu, vv[c], 16);
        out[c] = (k < 64) ? (vv[c] * cs - partner * sn) : (vv[c] * cs + partner * sn);
    }
    size_t base = (size_t)token * heads * KKD + head * KKD + lane * 4;
    __nv_bfloat162 h01, h23, l01, l23;
    h01.x = __float2bfloat16(out[0]); h01.y = __float2bfloat16(out[1]);
    h23.x = __float2bfloat16(out[2]); h23.y = __float2bfloat16(out[3]);
    l01.x = __float2bfloat16(out[0] - __bfloat162float(h01.x));
    l01.y = __float2bfloat16(out[1] - __bfloat162float(h01.y));
    l23.x = __float2bfloat16(out[2] - __bfloat162float(h23.x));
    l23.y = __float2bfloat16(out[3] - __bfloat162float(h23.y));
    *(__nv_bfloat162*)(hi + base) = h01; *(__nv_bfloat162*)(hi + base + 2) = h23;
    *(__nv_bfloat162*)(lo + base) = l01; *(__nv_bfloat162*)(lo + base + 2) = l23;
}

// ---------------- tensor-core flash attention, 2 heads per CTA ----------------
#define KVSTR 136
#define ABUF (64*KVSTR*2)                  /* 17408 B */
#define ATT_SMEM (6*ABUF + 256)

__global__ __launch_bounds__(256) void attn_mma_kernel() {
    extern __shared__ __align__(128) char smraw[];
    char* sQ = smraw;
    char* sKVhi = smraw + 4 * ABUF;
    char* sKVlo = smraw + 5 * ABUF;
    int* Sst = (int*)(smraw + 6 * ABUF);
    const uint32_t uKVhi = smem_u32(sKVhi);

    const int tid = threadIdx.x;
    const int warp = tid >> 5, lane = tid & 31;
    const int b = blockIdx.z;
    const int h0 = blockIdx.y * 2;
    const int hsub = warp >> 2;
    const int h = h0 + hsub;
    const int w4 = warp & 3;
    const int t0 = blockIdx.x * 64;
    const int g = h0 >> 2;
    const float scale = 0.08838834764831845f;
    const float NEG = -1e30f;

    const uint32_t uQ = smem_u32(sQ) + hsub * 2 * ABUF;

    {
        int hsel = tid >> 7;
        int r = (tid >> 1) & 63, half = tid & 1;
        size_t gofs = (size_t)(b * TT + t0 + r) * QW + (h0 + hsel) * KKD + half * 64;
        const uint4* sh = (const uint4*)(g_qhi + gofs);
        const uint4* sl = (const uint4*)(g_qlo + gofs);
        char* dh = sQ + hsel * 2 * ABUF + (r * KVSTR + half * 64) * 2;
#pragma unroll
        for (int i = 0; i < 8; i++) {
            ((uint4*)dh)[i] = sh[i];
            ((uint4*)(dh + ABUF))[i] = sl[i];
        }
    }
    if (tid < 64) {
        int t = t0 + tid;
        Sst[tid] = t - g_pos[b * TT + t];
    }
    __syncthreads();

    const int s_begin = Sst[0] & ~63;
    const int r_lo = w4 * 16 + (lane >> 2);
    const int t_0 = t0 + r_lo, t_1 = t_0 + 8;
    const int st0 = Sst[r_lo], st1 = Sst[r_lo + 8];
    const int qk = (lane & 3) << 1;

    float m0 = NEG, m1 = NEG, l0 = 0.f, l1 = 0.f;
    float o[16][4];
#pragma unroll
    for (int i = 0; i < 16; i++)
#pragma unroll
        for (int c = 0; c < 4; c++) o[i][c] = 0.f;

    for (int s0 = s_begin; s0 <= t0; s0 += 64) {
        {
            int r = tid >> 2, q4 = tid & 3;
            size_t gofs = (size_t)(b * TT + s0 + r) * KVW + g * KKD + q4 * 32;
            const uint4* sh = (const uint4*)(g_khi + gofs);
            const uint4* sl = (const uint4*)(g_klo + gofs);
            char* dh = sKVhi + (r * KVSTR + q4 * 32) * 2;
#pragma unroll
            for (int i = 0; i < 4; i++) {
                ((uint4*)dh)[i] = sh[i];
                ((uint4*)(dh + ABUF))[i] = sl[i];
            }
        }
        __syncthreads();

        float sfr[8][4];
#pragma unroll
        for (int i = 0; i < 8; i++)
#pragma unroll
            for (int c = 0; c < 4; c++) sfr[i][c] = 0.f;

#pragma unroll
        for (int k16 = 0; k16 < 8; k16++) {
            uint32_t qa = uQ + ((w4 * 16 + (lane & 15)) * KVSTR + k16 * 16 + ((lane >> 4) << 3)) * 2;
            uint32_t ah[4], al[4];
            ldm_x4(ah[0], ah[1], ah[2], ah[3], qa);
            ldm_x4(al[0], al[1], al[2], al[3], qa + ABUF);
#pragma unroll
            for (int f = 0; f < 4; f++) {
                uint32_t ka = uKVhi + ((f * 16 + (lane & 7) + ((lane >> 4) << 3)) * KVSTR
                                       + k16 * 16 + (((lane >> 3) & 1) << 3)) * 2;
                uint32_t bh[4], bl[4];
                ldm_x4(bh[0], bh[1], bh[2], bh[3], ka);
                ldm_x4(bl[0], bl[1], bl[2], bl[3], ka + ABUF);
                mma16816(sfr[2*f],   ah, bh);
                mma16816(sfr[2*f],   ah, bl);
                mma16816(sfr[2*f],   al, bh);
                mma16816(sfr[2*f+1], ah, bh + 2);
                mma16816(sfr[2*f+1], ah, bl + 2);
                mma16816(sfr[2*f+1], al, bh + 2);
            }
        }

        float rmax0 = NEG, rmax1 = NEG;
#pragma unroll
        for (int nf = 0; nf < 8; nf++) {
            int c0 = s0 + nf * 8 + qk, c1 = c0 + 1;
            sfr[nf][0] = (c0 <= t_0 && c0 >= st0) ? sfr[nf][0] * scale : NEG;
            sfr[nf][1] = (c1 <= t_0 && c1 >= st0) ? sfr[nf][1] * scale : NEG;
            sfr[nf][2] = (c0 <= t_1 && c0 >= st1) ? sfr[nf][2] * scale : NEG;
            sfr[nf][3] = (c1 <= t_1 && c1 >= st1) ? sfr[nf][3] * scale : NEG;
            rmax0 = fmaxf(rmax0, fmaxf(sfr[nf][0], sfr[nf][1]));
            rmax1 = fmaxf(rmax1, fmaxf(sfr[nf][2], sfr[nf][3]));
        }
        rmax0 = fmaxf(rmax0, __shfl_xor_sync(0xffffffffu, rmax0, 1));
        rmax0 = fmaxf(rmax0, __shfl_xor_sync(0xffffffffu, rmax0, 2));
        rmax1 = fmaxf(rmax1, __shfl_xor_sync(0xffffffffu, rmax1, 1));
        rmax1 = fmaxf(rmax1, __shfl_xor_sync(0xffffffffu, rmax1, 2));

        float mn0 = fmaxf(m0, rmax0), mn1 = fmaxf(m1, rmax1);
        float corr0 = __expf(m0 - mn0), corr1 = __expf(m1 - mn1);
        m0 = mn0; m1 = mn1;
        l0 *= corr0; l1 *= corr1;
#pragma unroll
        for (int i = 0; i < 16; i++) {
            o[i][0] *= corr0; o[i][1] *= corr0;
            o[i][2] *= corr1; o[i][3] *= corr1;
        }
        float sum0 = 0.f, sum1 = 0.f;
#pragma unroll
        for (int nf = 0; nf < 8; nf++) {
            float p0 = (sfr[nf][0] > -5e29f) ? __expf(sfr[nf][0] - mn0) : 0.f;
            float p1 = (sfr[nf][1] > -5e29f) ? __expf(sfr[nf][1] - mn0) : 0.f;
            float p2 = (sfr[nf][2] > -5e29f) ? __expf(sfr[nf][2] - mn1) : 0.f;
            float p3 = (sfr[nf][3] > -5e29f) ? __expf(sfr[nf][3] - mn1) : 0.f;
            sfr[nf][0] = p0; sfr[nf][1] = p1; sfr[nf][2] = p2; sfr[nf][3] = p3;
            sum0 += p0 + p1; sum1 += p2 + p3;
        }
        sum0 += __shfl_xor_sync(0xffffffffu, sum0, 1);
        sum0 += __shfl_xor_sync(0xffffffffu, sum0, 2);
        sum1 += __shfl_xor_sync(0xffffffffu, sum1, 1);
        sum1 += __shfl_xor_sync(0xffffffffu, sum1, 2);
        l0 += sum0; l1 += sum1;

        __syncthreads();

        {
            int r = tid >> 2, q4 = tid & 3;
            size_t gofs = (size_t)(b * TT + s0 + r) * KVW + g * KKD + q4 * 32;
            const uint4* sh = (const uint4*)(g_vhi + gofs);
            const uint4* sl = (const uint4*)(g_vlo + gofs);
            char* dh = sKVhi + (r * KVSTR + q4 * 32) * 2;
#pragma unroll
            for (int i = 0; i < 4; i++) {
                ((uint4*)dh)[i] = sh[i];
                ((uint4*)(dh + ABUF))[i] = sl[i];
            }
        }
        __syncthreads();

#pragma unroll
        for (int j = 0; j < 4; j++) {
            uint32_t ph[4], pl[4];
            ph[0] = pkhl(sfr[2*j][0],   sfr[2*j][1]);
            ph[1] = pkhl(sfr[2*j][2],   sfr[2*j][3]);
            ph[2] = pkhl(sfr[2*j+1][0], sfr[2*j+1][1]);
            ph[3] = pkhl(sfr[2*j+1][2], sfr[2*j+1][3]);
            pl[0] = pkhl(bfres(sfr[2*j][0]),   bfres(sfr[2*j][1]));
            pl[1] = pkhl(bfres(sfr[2*j][2]),   bfres(sfr[2*j][3]));
            pl[2] = pkhl(bfres(sfr[2*j+1][0]), bfres(sfr[2*j+1][1]));
            pl[3] = pkhl(bfres(sfr[2*j+1][2]), bfres(sfr[2*j+1][3]));
#pragma unroll
            for (int f = 0; f < 8; f++) {
                uint32_t va = uKVhi + ((j * 16 + (lane & 7) + (((lane >> 3) & 1) << 3)) * KVSTR
                                       + f * 16 + ((lane >> 4) << 3)) * 2;
                uint32_t vh[4], vl[4];
                ldm_x4t(vh[0], vh[1], vh[2], vh[3], va);
                ldm_x4t(vl[0], vl[1], vl[2], vl[3], va + ABUF);
                mma16816(o[2*f],   ph, vh);
                mma16816(o[2*f],   ph, vl);
                mma16816(o[2*f],   pl, vh);
                mma16816(o[2*f+1], ph, vh + 2);
                mma16816(o[2*f+1], ph, vl + 2);
                mma16816(o[2*f+1], pl, vh + 2);
            }
        }
        __syncthreads();
    }

    float inv0 = 1.0f / l0, inv1 = 1.0f / l1;
#pragma unroll
    for (int nf = 0; nf < 16; nf++) {
        int c = h * KKD + nf * 8 + qk;
        size_t a0 = (size_t)(b * TT + t_0) * QW + c;
        size_t a1 = (size_t)(b * TT + t_1) * QW + c;
        float v0 = o[nf][0] * inv0, v1 = o[nf][1] * inv0;
        float v2 = o[nf][2] * inv1, v3 = o[nf][3] * inv1;
        __nv_bfloat162 hh0, hh1, ll0, ll1;
        hh0.x = __float2bfloat16(v0); hh0.y = __float2bfloat16(v1);
        hh1.x = __float2bfloat16(v2); hh1.y = __float2bfloat16(v3);
        ll0.x = __float2bfloat16(v0 - __bfloat162float(hh0.x));
        ll0.y = __float2bfloat16(v1 - __bfloat162float(hh0.y));
        ll1.x = __float2bfloat16(v2 - __bfloat162float(hh1.x));
        ll1.y = __float2bfloat16(v3 - __bfloat162float(hh1.y));
        *(__nv_bfloat162*)(g_att_hi + a0) = hh0;
        *(__nv_bfloat162*)(g_att_lo + a0) = ll0;
        *(__nv_bfloat162*)(g_att_hi + a1) = hh1;
        *(__nv_bfloat162*)(g_att_lo + a1) = ll1;
    }
}

// ---------------- launch ----------------
extern "C" void kernel_launch(void* const* d_in, const int* in_sizes, int n_in,
                              void* d_out, int out_size) {
    const float* hidden  = (const float*)d_in[0];
    const float* wq      = (const float*)d_in[1];
    const float* wk      = (const float*)d_in[2];
    const float* wv      = (const float*)d_in[3];
    const float* wo      = (const float*)d_in[4];
    const float* q_scale = (const float*)d_in[5];
    const float* k_scale = (const float*)d_in[6];
    const int*   seg     = (const int*)d_in[7];
    float* out = (float*)d_out;

    float *q, *k;
    __nv_bfloat16 *hidh, *hidl, *atth, *attl;
    __nv_bfloat16 *qhi, *qlo, *khi, *klo;
    __nv_bfloat16 *wqh, *wql, *wkh, *wkl, *wvh, *wvl, *woh, *wol;
    cudaGetSymbolAddress((void**)&q, g_q);
    cudaGetSymbolAddress((void**)&k, g_k);
    cudaGetSymbolAddress((void**)&hidh, g_hid_hi);
    cudaGetSymbolAddress((void**)&hidl, g_hid_lo);
    cudaGetSymbolAddress((void**)&atth, g_att_hi);
    cudaGetSymbolAddress((void**)&attl, g_att_lo);
    cudaGetSymbolAddress((void**)&qhi, g_qhi);
    cudaGetSymbolAddress((void**)&qlo, g_qlo);
    cudaGetSymbolAddress((void**)&khi, g_khi);
    cudaGetSymbolAddress((void**)&klo, g_klo);
    cudaGetSymbolAddress((void**)&wqh, g_wq_hi);
    cudaGetSymbolAddress((void**)&wql, g_wq_lo);
    cudaGetSymbolAddress((void**)&wkh, g_wk_hi);
    cudaGetSymbolAddress((void**)&wkl, g_wk_lo);
    cudaGetSymbolAddress((void**)&wvh, g_wv_hi);
    cudaGetSymbolAddress((void**)&wvl, g_wv_lo);
    cudaGetSymbolAddress((void**)&woh, g_wo_hi);
    cudaGetSymbolAddress((void**)&wol, g_wo_lo);

    cudaFuncSetAttribute(qkv_gemm_kernel, cudaFuncAttributeMaxDynamicSharedMemorySize, GSM);
    cudaFuncSetAttribute(mma_gemm_kernel, cudaFuncAttributeMaxDynamicSharedMemorySize, GSM);
    cudaFuncSetAttribute(attn_mma_kernel, cudaFuncAttributeMaxDynamicSharedMemorySize, ATT_SMEM);

    pos_kernel<<<NTOK / 256, 256>>>(seg);
    {
        int n4 = NTOK * DD / 4;
        split_kernel<<<(n4 + 255) / 256, 256>>>(hidden, hidh, hidl, n4);
    }
    tsplit_kernel<<<dim3(QW / 32, DD / 32), dim3(32, 8)>>>(wq, wqh, wql, DD, QW);
    tsplit_kernel<<<dim3(KVW / 32, DD / 32), dim3(32, 8)>>>(wk, wkh, wkl, DD, KVW);
    tsplit_kernel<<<dim3(KVW / 32, DD / 32), dim3(32, 8)>>>(wv, wvh, wvl, DD, KVW);

    qkv_gemm_kernel<<<dim3(12, NTOK / 128), 256, GSM>>>(hidh, hidl);

    normrope_kernel<<<(NTOK * HH) / 8, 256>>>(q, q_scale, qhi, qlo, HH);
    normrope_kernel<<<(NTOK * GG) / 8, 256>>>(k, k_scale, khi, klo, GG);

    attn_mma_kernel<<<dim3(TT / 64, HH / 2, BB), 256, ATT_SMEM>>>();

    tsplit_kernel<<<dim3(DD / 32, QW / 32), dim3(32, 8)>>>(wo, woh, wol, QW, DD);

    mma_gemm_kernel<<<dim3(DD / 256, NTOK / 128), 256, GSM>>>(
        atth, attl, woh, wol, out, DD, QW);
}